// round 9
// baseline (speedup 1.0000x reference)
#include <cuda_runtime.h>
#include <cuda_bf16.h>
#include <math.h>
#include <stdint.h>

typedef __nv_bfloat16 bf16;

#define BBATCH 4
#define SSEQ 4096
#define DDIM 1024
#define FFREQ 256
#define TWO_F 512
#define MROWS (BBATCH*SSEQ)     // 16384
#define EPSF 1e-5f
#define CHUNKS 32
#define CLEN (SSEQ/CHUNKS)      // 128

// ---- GEMM tiling ----
#define BM 128
#define BN 256
#define BK 32
#define NSTAGE 4
#define ROWB 80                        // padded row bytes (32 bf16 -> 80B, 16B aligned)
#define A_BYTES (BM*ROWB)              // 10240
#define B_BYTES (BN*ROWB)              // 20480
#define STAGE_BYTES (A_BYTES+B_BYTES)  // 30720
#define SMEM_SZ (NSTAGE*STAGE_BYTES)   // 122880

// ---------------- scratch (device globals) ----------------
__device__ bf16  g_xhi[(size_t)MROWS*DDIM];
__device__ bf16  g_xlo[(size_t)MROWS*DDIM];
__device__ float g_spec[(size_t)MROWS*TWO_F];
__device__ bf16  g_shi[(size_t)MROWS*TWO_F];
__device__ bf16  g_slo[(size_t)MROWS*TWO_F];
__device__ bf16  g_chi[(size_t)MROWS*DDIM];
__device__ bf16  g_clo[(size_t)MROWS*DDIM];
__device__ bf16  g_hhi[(size_t)MROWS*DDIM];
__device__ bf16  g_hlo[(size_t)MROWS*DDIM];
__device__ float g_h2[(size_t)MROWS*DDIM];
__device__ bf16  g_wspec_hi[TWO_F*DDIM], g_wspec_lo[TWO_F*DDIM];
__device__ bf16  g_wfrom_hi[DDIM*TWO_F], g_wfrom_lo[DDIM*TWO_F];
__device__ bf16  g_w1_hi[DDIM*DDIM],    g_w1_lo[DDIM*DDIM];
__device__ bf16  g_w2_hi[DDIM*DDIM],    g_w2_lo[DDIM*DDIM];
__device__ float2 g_hend[BBATCH*CHUNKS*FFREQ];
__device__ float2 g_carry[BBATCH*CHUNKS*FFREQ];
__device__ float g_errpart[512];

// ---------------- PTX helpers ----------------
__device__ __forceinline__ uint32_t smem_u32(const void* p) {
    uint32_t a;
    asm("{ .reg .u64 t; cvta.to.shared.u64 t, %1; cvt.u32.u64 %0, t; }" : "=r"(a) : "l"(p));
    return a;
}
__device__ __forceinline__ void cp16(uint32_t s, const void* g) {
    asm volatile("cp.async.cg.shared.global [%0], [%1], 16;" :: "r"(s), "l"(g));
}
__device__ __forceinline__ void ldm_x4(uint32_t& r0, uint32_t& r1, uint32_t& r2,
                                       uint32_t& r3, uint32_t addr) {
    asm volatile("ldmatrix.sync.aligned.m8n8.x4.shared.b16 {%0,%1,%2,%3}, [%4];"
        : "=r"(r0), "=r"(r1), "=r"(r2), "=r"(r3) : "r"(addr));
}
__device__ __forceinline__ void mma16816(float* c, const uint32_t* a, const uint32_t* b) {
    asm volatile("mma.sync.aligned.m16n8k16.row.col.f32.bf16.bf16.f32 "
        "{%0,%1,%2,%3}, {%4,%5,%6,%7}, {%8,%9}, {%0,%1,%2,%3};"
        : "+f"(c[0]), "+f"(c[1]), "+f"(c[2]), "+f"(c[3])
        : "r"(a[0]), "r"(a[1]), "r"(a[2]), "r"(a[3]), "r"(b[0]), "r"(b[1]));
}

// hi/lo split helpers
__device__ __forceinline__ uint32_t pack_hi2(float a, float b, float& ra, float& rb) {
    __nv_bfloat16 ha = __float2bfloat16(a), hb = __float2bfloat16(b);
    ra = a - __bfloat162float(ha);
    rb = b - __bfloat162float(hb);
    __nv_bfloat162 t; t.x = ha; t.y = hb;
    return *reinterpret_cast<uint32_t*>(&t);
}
__device__ __forceinline__ uint32_t pack_lo2(float a, float b) {
    __nv_bfloat162 t; t.x = __float2bfloat16(a); t.y = __float2bfloat16(b);
    return *reinterpret_cast<uint32_t*>(&t);
}

// ====================== weight split ======================
__global__ void split_k(const float4* __restrict__ x, uint2* __restrict__ hi,
                        uint2* __restrict__ lo, int n4) {
    int i = blockIdx.x * blockDim.x + threadIdx.x;
    if (i >= n4) return;
    float4 v = x[i];
    float r0, r1, r2, r3;
    uint2 h, l;
    h.x = pack_hi2(v.x, v.y, r0, r1);
    h.y = pack_hi2(v.z, v.w, r2, r3);
    l.x = pack_lo2(r0, r1);
    l.y = pack_lo2(r2, r3);
    hi[i] = h; lo[i] = l;
}

// ====================== LayerNorm ======================
template <int OUT_BF16>
__global__ void ln_kernel(const float* __restrict__ x, const float* __restrict__ g,
                          const float* __restrict__ b, float* __restrict__ out,
                          bf16* __restrict__ ohi, bf16* __restrict__ olo) {
    int row = blockIdx.x;
    int t = threadIdx.x;
    const float4* xr = (const float4*)(x + (size_t)row * DDIM);
    float4 v = xr[t];
    float s = v.x + v.y + v.z + v.w;
    float q = v.x*v.x + v.y*v.y + v.z*v.z + v.w*v.w;
    __shared__ float ss[8], sq[8];
    #pragma unroll
    for (int o = 16; o > 0; o >>= 1) {
        s += __shfl_down_sync(0xffffffffu, s, o);
        q += __shfl_down_sync(0xffffffffu, q, o);
    }
    int w = t >> 5, l = t & 31;
    if (l == 0) { ss[w] = s; sq[w] = q; }
    __syncthreads();
    if (w == 0) {
        s = (l < 8) ? ss[l] : 0.f;
        q = (l < 8) ? sq[l] : 0.f;
        #pragma unroll
        for (int o = 4; o > 0; o >>= 1) {
            s += __shfl_down_sync(0xffffffffu, s, o);
            q += __shfl_down_sync(0xffffffffu, q, o);
        }
        if (l == 0) { ss[0] = s; sq[0] = q; }
    }
    __syncthreads();
    float mu  = ss[0] * (1.f / DDIM);
    float var = sq[0] * (1.f / DDIM) - mu * mu;
    float rs  = rsqrtf(var + EPSF);
    float4 gv = ((const float4*)g)[t];
    float4 bv = ((const float4*)b)[t];
    float4 o4;
    o4.x = (v.x - mu) * rs * gv.x + bv.x;
    o4.y = (v.y - mu) * rs * gv.y + bv.y;
    o4.z = (v.z - mu) * rs * gv.z + bv.z;
    o4.w = (v.w - mu) * rs * gv.w + bv.w;
    if (OUT_BF16) {
        float r0, r1, r2, r3;
        uint2 h, lv;
        h.x = pack_hi2(o4.x, o4.y, r0, r1);
        h.y = pack_hi2(o4.z, o4.w, r2, r3);
        lv.x = pack_lo2(r0, r1);
        lv.y = pack_lo2(r2, r3);
        ((uint2*)(ohi + (size_t)row * DDIM))[t] = h;
        ((uint2*)(olo + (size_t)row * DDIM))[t] = lv;
    } else {
        ((float4*)(out + (size_t)row * DDIM))[t] = o4;
    }
}

// ====================== mma.sync GEMM ======================
// C[m,n] = sum_k A[m,k]*B[n,k] (NT), fp32 accum via 3-term bf16 split.
// CTA 128x256, 8 warps (2M x 4N), warp tile 64x64.
// EPI: 0 = fp32 store, 2 = corrected (fp32 + hi/lo + err), 3 = bias+gelu (hi/lo), 4 = bias (fp32)
template <int EPI>
__global__ void __launch_bounds__(256, 1)
gemm_mma(const bf16* __restrict__ Ahi, const bf16* __restrict__ Alo,
         const bf16* __restrict__ Bhi, const bf16* __restrict__ Blo,
         float* __restrict__ Cf, bf16* __restrict__ Chi, bf16* __restrict__ Clo,
         int K, int N,
         const float* __restrict__ bias, const float* __restrict__ td,
         const float* __restrict__ ew, float* __restrict__ errpart) {
    extern __shared__ __align__(128) char smem[];
    __shared__ float red[8];
    const uint32_t sb = smem_u32(smem);
    const int tid = threadIdx.x;
    const int wid = tid >> 5, lane = tid & 31;
    const int mBase = blockIdx.y * BM;
    const int nBase = blockIdx.x * BN;
    const int kc = K >> 5;
    const int NK = 3 * kc;

    const int wm = (wid >> 2) * 64;     // warp m offset (0/64)
    const int wn = (wid & 3) * 64;      // warp n offset (0/64/128/192)

    // ldmatrix per-thread base offsets (within a stage's A/B region)
    const uint32_t a_off = (uint32_t)(wm + (lane & 15)) * ROWB + ((lane >> 4) * 8) * 2;
    const uint32_t b_off = (uint32_t)(wn + ((lane >> 4) << 3) + (lane & 7)) * ROWB
                         + (((lane >> 3) & 1) * 8) * 2;

    float acc[4][8][4];
    #pragma unroll
    for (int i = 0; i < 4; i++)
        #pragma unroll
        for (int j = 0; j < 8; j++)
            #pragma unroll
            for (int q = 0; q < 4; q++) acc[i][j][q] = 0.f;

    auto load_stage = [&](int kt, int s) {
        int term = kt / kc;
        int kk = kt - term * kc;
        const bf16* As = (term < 2) ? Ahi : Alo;
        const bf16* Bs = (term == 1) ? Blo : Bhi;
        size_t koff = (size_t)kk * BK;
        uint32_t abase = sb + s * STAGE_BYTES;
        uint32_t bbase = abase + A_BYTES;
        #pragma unroll
        for (int r = 0; r < 2; r++) {
            int ch = tid + 256 * r;                 // 0..511
            int row = ch >> 2, c16 = ch & 3;
            cp16(abase + row * ROWB + c16 * 16,
                 As + (size_t)(mBase + row) * K + koff + c16 * 8);
        }
        #pragma unroll
        for (int r = 0; r < 4; r++) {
            int ch = tid + 256 * r;                 // 0..1023
            int row = ch >> 2, c16 = ch & 3;
            cp16(bbase + row * ROWB + c16 * 16,
                 Bs + (size_t)(nBase + row) * K + koff + c16 * 8);
        }
        asm volatile("cp.async.commit_group;" ::: "memory");
    };

    // prologue: 3 stages in flight
    #pragma unroll
    for (int kt = 0; kt < NSTAGE - 1; kt++)
        if (kt < NK) load_stage(kt, kt);

    for (int kt = 0; kt < NK; kt++) {
        int rem = NK - 1 - kt;
        if (rem >= 2)      asm volatile("cp.async.wait_group 2;" ::: "memory");
        else if (rem == 1) asm volatile("cp.async.wait_group 1;" ::: "memory");
        else               asm volatile("cp.async.wait_group 0;" ::: "memory");
        __syncthreads();
        if (kt + NSTAGE - 1 < NK) load_stage(kt + NSTAGE - 1, (kt + NSTAGE - 1) & 3);

        uint32_t abase = sb + (kt & 3) * STAGE_BYTES;
        uint32_t bbase = abase + A_BYTES;
        #pragma unroll
        for (int ks = 0; ks < 2; ks++) {
            uint32_t af[4][4], bfr[8][2];
            #pragma unroll
            for (int mi = 0; mi < 4; mi++)
                ldm_x4(af[mi][0], af[mi][1], af[mi][2], af[mi][3],
                       abase + a_off + mi * 16 * ROWB + ks * 32);
            #pragma unroll
            for (int n2 = 0; n2 < 4; n2++)
                ldm_x4(bfr[2*n2][0], bfr[2*n2][1], bfr[2*n2+1][0], bfr[2*n2+1][1],
                       bbase + b_off + n2 * 16 * ROWB + ks * 32);
            #pragma unroll
            for (int mi = 0; mi < 4; mi++)
                #pragma unroll
                for (int ni = 0; ni < 8; ni++)
                    mma16816(acc[mi][ni], af[mi], bfr[ni]);
        }
    }

    // ---- epilogue ----
    const int g = lane >> 2, tig = lane & 3;
    float esum = 0.f;
    float sw_ = 0.f;
    if (EPI == 2) sw_ = 1.f / (1.f + expf(-ew[0]));

    #pragma unroll
    for (int mi = 0; mi < 4; mi++) {
        #pragma unroll
        for (int half = 0; half < 2; half++) {
            int row = mBase + wm + mi * 16 + g + half * 8;
            #pragma unroll
            for (int ni = 0; ni < 8; ni++) {
                int col = nBase + wn + ni * 8 + 2 * tig;
                float c0 = acc[mi][ni][half * 2 + 0];
                float c1 = acc[mi][ni][half * 2 + 1];
                if (EPI == 2) {
                    float2 tv = *(const float2*)(td + (size_t)row * N + col);
                    float e0 = fminf(1.f, fmaxf(-1.f, c0 - tv.x));
                    float e1 = fminf(1.f, fmaxf(-1.f, c1 - tv.y));
                    esum += e0 * e0 + e1 * e1;
                    c0 -= sw_ * e0;
                    c1 -= sw_ * e1;
                } else if (EPI == 3) {
                    float2 bv = *(const float2*)(bias + col);
                    float v0 = c0 + bv.x, v1 = c1 + bv.y;
                    c0 = 0.5f * v0 * (1.f + erff(v0 * 0.70710678118f));
                    c1 = 0.5f * v1 * (1.f + erff(v1 * 0.70710678118f));
                } else if (EPI == 4) {
                    float2 bv = *(const float2*)(bias + col);
                    c0 += bv.x; c1 += bv.y;
                }
                if (EPI == 0 || EPI == 2 || EPI == 4)
                    *(float2*)(Cf + (size_t)row * N + col) = make_float2(c0, c1);
                if (EPI == 2 || EPI == 3) {
                    float r0, r1;
                    uint32_t hbits = pack_hi2(c0, c1, r0, r1);
                    uint32_t lbits = pack_lo2(r0, r1);
                    *(uint32_t*)(Chi + (size_t)row * N + col) = hbits;
                    *(uint32_t*)(Clo + (size_t)row * N + col) = lbits;
                }
            }
        }
    }

    if (EPI == 2) {
        #pragma unroll
        for (int o2 = 16; o2 > 0; o2 >>= 1)
            esum += __shfl_down_sync(0xffffffffu, esum, o2);
        if (lane == 0) red[wid] = esum;
        __syncthreads();
        if (tid == 0) {
            float s2 = 0.f;
            #pragma unroll
            for (int i = 0; i < 8; i++) s2 += red[i];
            errpart[blockIdx.y * gridDim.x + blockIdx.x] = s2;
        }
    }
}

// ====================== spectral scan ======================
__device__ __forceinline__ float2 cmulf(float2 a, float2 b) {
    return make_float2(a.x * b.x - a.y * b.y, a.x * b.y + a.y * b.x);
}
__device__ __forceinline__ void scan_consts(const float* ld, const float* fr, int f,
                                            float2& A, float2& rot) {
    float decay = 1.f / (1.f + expf(-ld[f]));
    float om = tanhf(fr[f]) * 0.1f;
    rot = make_float2(cosf(om), sinf(om));
    A = make_float2(decay * rot.x, decay * rot.y);
}

__global__ void scan_phaseA(const float* __restrict__ ld, const float* __restrict__ fr) {
    int b = blockIdx.x / CHUNKS, c = blockIdx.x % CHUNKS;
    int f = threadIdx.x;
    float2 A, rot;
    scan_consts(ld, fr, f, A, rot);
    float2 h = make_float2(0.f, 0.f);
    const float* base = g_spec + ((size_t)b * SSEQ + (size_t)c * CLEN) * TWO_F;
    #pragma unroll 4
    for (int j = 0; j < CLEN; j++) {
        float ur = base[(size_t)j * TWO_F + f];
        float ui = base[(size_t)j * TWO_F + FFREQ + f];
        float hr = A.x * h.x - A.y * h.y + ur;
        float hi = A.x * h.y + A.y * h.x + ui;
        h.x = hr; h.y = hi;
    }
    g_hend[(b * CHUNKS + c) * FFREQ + f] = h;
}

__global__ void scan_carry(const float* __restrict__ ld, const float* __restrict__ fr) {
    int b = blockIdx.x;
    int f = threadIdx.x;
    float2 A, rot;
    scan_consts(ld, fr, f, A, rot);
    float2 AL = A;
    #pragma unroll
    for (int i = 0; i < 7; i++) AL = cmulf(AL, AL);   // A^128
    float2 H = make_float2(0.f, 0.f);
    for (int c = 0; c < CHUNKS; c++) {
        g_carry[(b * CHUNKS + c) * FFREQ + f] = H;
        float2 he = g_hend[(b * CHUNKS + c) * FFREQ + f];
        float hr = AL.x * H.x - AL.y * H.y + he.x;
        float hi = AL.x * H.y + AL.y * H.x + he.y;
        H.x = hr; H.y = hi;
    }
}

__global__ void scan_phaseC(const float* __restrict__ ld, const float* __restrict__ fr) {
    int b = blockIdx.x / CHUNKS, c = blockIdx.x % CHUNKS;
    int f = threadIdx.x;
    float2 A, rot;
    scan_consts(ld, fr, f, A, rot);
    float2 h = g_carry[(b * CHUNKS + c) * FFREQ + f];
    size_t rowoff = ((size_t)b * SSEQ + (size_t)c * CLEN) * TWO_F;
    const float* base = g_spec + rowoff;
    #pragma unroll 4
    for (int j = 0; j < CLEN; j++) {
        float ur = base[(size_t)j * TWO_F + f];
        float ui = base[(size_t)j * TWO_F + FFREQ + f];
        float hr = A.x * h.x - A.y * h.y + ur;
        float hi = A.x * h.y + A.y * h.x + ui;
        h.x = hr; h.y = hi;
        float yr = rot.x * hr - rot.y * hi;
        float yi = rot.x * hi + rot.y * hr;
        size_t ir = rowoff + (size_t)j * TWO_F + f;
        size_t ii = rowoff + (size_t)j * TWO_F + FFREQ + f;
        __nv_bfloat16 hr16 = __float2bfloat16(yr);
        __nv_bfloat16 hi16 = __float2bfloat16(yi);
        g_shi[ir] = hr16;
        g_slo[ir] = __float2bfloat16(yr - __bfloat162float(hr16));
        g_shi[ii] = hi16;
        g_slo[ii] = __float2bfloat16(yi - __bfloat162float(hi16));
    }
}

// ======================= error finalize =======================
__global__ void err_finish(float* __restrict__ o) {
    int t = threadIdx.x;   // 512 threads
    double v = (double)g_errpart[t];
    #pragma unroll
    for (int off = 16; off > 0; off >>= 1)
        v += __shfl_down_sync(0xffffffffu, v, off);
    __shared__ double sh[16];
    int w = t >> 5, l = t & 31;
    if (l == 0) sh[w] = v;
    __syncthreads();
    if (t < 16) {
        v = sh[t];
        #pragma unroll
        for (int off = 8; off > 0; off >>= 1)
            v += __shfl_down_sync(0xffffu, v, off);
        if (t == 0) {
            double mean = v / ((double)MROWS * (double)DDIM);
            float m = (float)mean;
            m = fminf(1.f, fmaxf(0.f, m));
            o[0] = m;
        }
    }
}

// ============================ launch ============================
extern "C" void kernel_launch(void* const* d_in, const int* in_sizes, int n_in,
                              void* d_out, int out_size) {
    const float* bu      = (const float*)d_in[0];
    const float* td      = (const float*)d_in[1];
    const float* W_spec  = (const float*)d_in[2];
    const float* log_dec = (const float*)d_in[3];
    const float* freq    = (const float*)d_in[4];
    const float* W_from  = (const float*)d_in[5];
    const float* ln1g    = (const float*)d_in[6];
    const float* ln1b    = (const float*)d_in[7];
    const float* W1      = (const float*)d_in[8];
    const float* b1      = (const float*)d_in[9];
    const float* W2      = (const float*)d_in[10];
    const float* b2      = (const float*)d_in[11];
    const float* ln2g    = (const float*)d_in[12];
    const float* ln2b    = (const float*)d_in[13];
    const float* ew      = (const float*)d_in[14];

    float* out       = (float*)d_out;
    float* corrected = out;
    float* nextpred  = out + (size_t)MROWS * DDIM;
    float* errout    = out + 2 * (size_t)MROWS * DDIM;

    bf16 *xhi, *xlo, *shi, *slo, *chi, *clo, *hhi, *hlo;
    bf16 *wsh, *wsl, *wfh, *wfl, *w1h, *w1l, *w2h, *w2l;
    float *spec, *h2, *errpart;
    cudaGetSymbolAddress((void**)&xhi, g_xhi);   cudaGetSymbolAddress((void**)&xlo, g_xlo);
    cudaGetSymbolAddress((void**)&shi, g_shi);   cudaGetSymbolAddress((void**)&slo, g_slo);
    cudaGetSymbolAddress((void**)&chi, g_chi);   cudaGetSymbolAddress((void**)&clo, g_clo);
    cudaGetSymbolAddress((void**)&hhi, g_hhi);   cudaGetSymbolAddress((void**)&hlo, g_hlo);
    cudaGetSymbolAddress((void**)&wsh, g_wspec_hi); cudaGetSymbolAddress((void**)&wsl, g_wspec_lo);
    cudaGetSymbolAddress((void**)&wfh, g_wfrom_hi); cudaGetSymbolAddress((void**)&wfl, g_wfrom_lo);
    cudaGetSymbolAddress((void**)&w1h, g_w1_hi);    cudaGetSymbolAddress((void**)&w1l, g_w1_lo);
    cudaGetSymbolAddress((void**)&w2h, g_w2_hi);    cudaGetSymbolAddress((void**)&w2l, g_w2_lo);
    cudaGetSymbolAddress((void**)&spec, g_spec);
    cudaGetSymbolAddress((void**)&h2, g_h2);
    cudaGetSymbolAddress((void**)&errpart, g_errpart);

    cudaFuncSetAttribute(gemm_mma<0>, cudaFuncAttributeMaxDynamicSharedMemorySize, SMEM_SZ);
    cudaFuncSetAttribute(gemm_mma<2>, cudaFuncAttributeMaxDynamicSharedMemorySize, SMEM_SZ);
    cudaFuncSetAttribute(gemm_mma<3>, cudaFuncAttributeMaxDynamicSharedMemorySize, SMEM_SZ);
    cudaFuncSetAttribute(gemm_mma<4>, cudaFuncAttributeMaxDynamicSharedMemorySize, SMEM_SZ);

    int n4 = TWO_F * DDIM / 4;
    int m4 = DDIM * DDIM / 4;
    // launches 0-3: weight splits (so launch #5 below is a GEMM for ncu -s 5)
    split_k<<<(m4 + 255) / 256, 256>>>((const float4*)W1, (uint2*)w1h, (uint2*)w1l, m4);
    split_k<<<(m4 + 255) / 256, 256>>>((const float4*)W2, (uint2*)w2h, (uint2*)w2l, m4);
    split_k<<<(n4 + 255) / 256, 256>>>((const float4*)W_spec, (uint2*)wsh, (uint2*)wsl, n4);
    split_k<<<(n4 + 255) / 256, 256>>>((const float4*)W_from, (uint2*)wfh, (uint2*)wfl, n4);

    // 4) LN1 -> xln hi/lo
    ln_kernel<1><<<MROWS, 256>>>(bu, ln1g, ln1b, nullptr, xhi, xlo);
    // 5) spec = xln @ W_spec^T   (launch index 5 -> profiled by ncu)
    gemm_mma<0><<<dim3(TWO_F / BN, MROWS / BM), 256, SMEM_SZ>>>(
        xhi, xlo, wsh, wsl, spec, nullptr, nullptr, DDIM, TWO_F,
        nullptr, nullptr, nullptr, nullptr);
    // chunked complex scan -> sout hi/lo
    scan_phaseA<<<BBATCH * CHUNKS, FFREQ>>>(log_dec, freq);
    scan_carry<<<BBATCH, FFREQ>>>(log_dec, freq);
    scan_phaseC<<<BBATCH * CHUNKS, FFREQ>>>(log_dec, freq);
    // corrected = sout @ W_from^T (+ err)
    gemm_mma<2><<<dim3(DDIM / BN, MROWS / BM), 256, SMEM_SZ>>>(
        shi, slo, wfh, wfl, corrected, chi, clo, TWO_F, DDIM,
        nullptr, td, ew, errpart);
    err_finish<<<1, 512>>>(errout);
    // h = gelu(corrected @ W1^T + b1)
    gemm_mma<3><<<dim3(DDIM / BN, MROWS / BM), 256, SMEM_SZ>>>(
        chi, clo, w1h, w1l, nullptr, hhi, hlo, DDIM, DDIM,
        b1, nullptr, nullptr, nullptr);
    // h2 = h @ W2^T + b2
    gemm_mma<4><<<dim3(DDIM / BN, MROWS / BM), 256, SMEM_SZ>>>(
        hhi, hlo, w2h, w2l, h2, nullptr, nullptr, DDIM, DDIM,
        b2, nullptr, nullptr, nullptr);
    // LN2 -> next_prediction
    ln_kernel<0><<<MROWS, 256>>>(h2, ln2g, ln2b, nextpred, nullptr, nullptr);
}

// round 13
// speedup vs baseline: 1.3856x; 1.3856x over previous
#include <cuda_runtime.h>
#include <cuda_bf16.h>
#include <math.h>
#include <stdint.h>

typedef __nv_bfloat16 bf16;

#define BBATCH 4
#define SSEQ 4096
#define DDIM 1024
#define FFREQ 256
#define TWO_F 512
#define MROWS (BBATCH*SSEQ)     // 16384
#define EPSF 1e-5f
#define CHUNKS 32
#define CLEN (SSEQ/CHUNKS)      // 128

// ---- GEMM tiling ----
#define BM 128
#define BN 128
#define BK 64
#define NSTAGE 3
#define ROWB 144                       // 64 bf16 = 128B + 16B pad
#define A_BYTES (BM*ROWB)              // 18432
#define B_BYTES (BN*ROWB)              // 18432
#define STAGE_BYTES (A_BYTES+B_BYTES)  // 36864
#define SMEM_SZ (NSTAGE*STAGE_BYTES)   // 110592

// ---------------- scratch (device globals) ----------------
__device__ bf16  g_xhi[(size_t)MROWS*DDIM];
__device__ bf16  g_xlo[(size_t)MROWS*DDIM];
__device__ float g_spec[(size_t)MROWS*TWO_F];
__device__ bf16  g_shi[(size_t)MROWS*TWO_F];
__device__ bf16  g_slo[(size_t)MROWS*TWO_F];
__device__ bf16  g_chi[(size_t)MROWS*DDIM];
__device__ bf16  g_clo[(size_t)MROWS*DDIM];
__device__ bf16  g_hhi[(size_t)MROWS*DDIM];
__device__ bf16  g_hlo[(size_t)MROWS*DDIM];
__device__ float g_h2[(size_t)MROWS*DDIM];
__device__ bf16  g_wspec_hi[TWO_F*DDIM], g_wspec_lo[TWO_F*DDIM];
__device__ bf16  g_wfrom_hi[DDIM*TWO_F], g_wfrom_lo[DDIM*TWO_F];
__device__ bf16  g_w1_hi[DDIM*DDIM],    g_w1_lo[DDIM*DDIM];
__device__ bf16  g_w2_hi[DDIM*DDIM],    g_w2_lo[DDIM*DDIM];
__device__ float2 g_hend[BBATCH*CHUNKS*FFREQ];
__device__ float2 g_carry[BBATCH*CHUNKS*FFREQ];
__device__ float g_errpart[1024];

// ---------------- PTX helpers ----------------
__device__ __forceinline__ uint32_t smem_u32(const void* p) {
    uint32_t a;
    asm("{ .reg .u64 t; cvta.to.shared.u64 t, %1; cvt.u32.u64 %0, t; }" : "=r"(a) : "l"(p));
    return a;
}
__device__ __forceinline__ void cp16(uint32_t s, const void* g) {
    asm volatile("cp.async.cg.shared.global [%0], [%1], 16;" :: "r"(s), "l"(g));
}
__device__ __forceinline__ void ldm_x4(uint32_t& r0, uint32_t& r1, uint32_t& r2,
                                       uint32_t& r3, uint32_t addr) {
    asm volatile("ldmatrix.sync.aligned.m8n8.x4.shared.b16 {%0,%1,%2,%3}, [%4];"
        : "=r"(r0), "=r"(r1), "=r"(r2), "=r"(r3) : "r"(addr));
}
__device__ __forceinline__ void mma16816(float* c, const uint32_t* a, const uint32_t* b) {
    asm volatile("mma.sync.aligned.m16n8k16.row.col.f32.bf16.bf16.f32 "
        "{%0,%1,%2,%3}, {%4,%5,%6,%7}, {%8,%9}, {%0,%1,%2,%3};"
        : "+f"(c[0]), "+f"(c[1]), "+f"(c[2]), "+f"(c[3])
        : "r"(a[0]), "r"(a[1]), "r"(a[2]), "r"(a[3]), "r"(b[0]), "r"(b[1]));
}

// hi/lo split helpers
__device__ __forceinline__ uint32_t pack_hi2(float a, float b, float& ra, float& rb) {
    __nv_bfloat16 ha = __float2bfloat16(a), hb = __float2bfloat16(b);
    ra = a - __bfloat162float(ha);
    rb = b - __bfloat162float(hb);
    __nv_bfloat162 t; t.x = ha; t.y = hb;
    return *reinterpret_cast<uint32_t*>(&t);
}
__device__ __forceinline__ uint32_t pack_lo2(float a, float b) {
    __nv_bfloat162 t; t.x = __float2bfloat16(a); t.y = __float2bfloat16(b);
    return *reinterpret_cast<uint32_t*>(&t);
}

// ====================== weight split ======================
__global__ void split_k(const float4* __restrict__ x, uint2* __restrict__ hi,
                        uint2* __restrict__ lo, int n4) {
    int i = blockIdx.x * blockDim.x + threadIdx.x;
    if (i >= n4) return;
    float4 v = x[i];
    float r0, r1, r2, r3;
    uint2 h, l;
    h.x = pack_hi2(v.x, v.y, r0, r1);
    h.y = pack_hi2(v.z, v.w, r2, r3);
    l.x = pack_lo2(r0, r1);
    l.y = pack_lo2(r2, r3);
    hi[i] = h; lo[i] = l;
}

// ====================== LayerNorm ======================
template <int OUT_BF16>
__global__ void ln_kernel(const float* __restrict__ x, const float* __restrict__ g,
                          const float* __restrict__ b, float* __restrict__ out,
                          bf16* __restrict__ ohi, bf16* __restrict__ olo) {
    int row = blockIdx.x;
    int t = threadIdx.x;
    const float4* xr = (const float4*)(x + (size_t)row * DDIM);
    float4 v = xr[t];
    float s = v.x + v.y + v.z + v.w;
    float q = v.x*v.x + v.y*v.y + v.z*v.z + v.w*v.w;
    __shared__ float ss[8], sq[8];
    #pragma unroll
    for (int o = 16; o > 0; o >>= 1) {
        s += __shfl_down_sync(0xffffffffu, s, o);
        q += __shfl_down_sync(0xffffffffu, q, o);
    }
    int w = t >> 5, l = t & 31;
    if (l == 0) { ss[w] = s; sq[w] = q; }
    __syncthreads();
    if (w == 0) {
        s = (l < 8) ? ss[l] : 0.f;
        q = (l < 8) ? sq[l] : 0.f;
        #pragma unroll
        for (int o = 4; o > 0; o >>= 1) {
            s += __shfl_down_sync(0xffffffffu, s, o);
            q += __shfl_down_sync(0xffffffffu, q, o);
        }
        if (l == 0) { ss[0] = s; sq[0] = q; }
    }
    __syncthreads();
    float mu  = ss[0] * (1.f / DDIM);
    float var = sq[0] * (1.f / DDIM) - mu * mu;
    float rs  = rsqrtf(var + EPSF);
    float4 gv = ((const float4*)g)[t];
    float4 bv = ((const float4*)b)[t];
    float4 o4;
    o4.x = (v.x - mu) * rs * gv.x + bv.x;
    o4.y = (v.y - mu) * rs * gv.y + bv.y;
    o4.z = (v.z - mu) * rs * gv.z + bv.z;
    o4.w = (v.w - mu) * rs * gv.w + bv.w;
    if (OUT_BF16) {
        float r0, r1, r2, r3;
        uint2 h, lv;
        h.x = pack_hi2(o4.x, o4.y, r0, r1);
        h.y = pack_hi2(o4.z, o4.w, r2, r3);
        lv.x = pack_lo2(r0, r1);
        lv.y = pack_lo2(r2, r3);
        ((uint2*)(ohi + (size_t)row * DDIM))[t] = h;
        ((uint2*)(olo + (size_t)row * DDIM))[t] = lv;
    } else {
        ((float4*)(out + (size_t)row * DDIM))[t] = o4;
    }
}

// ====================== mma.sync GEMM ======================
// C[m,n] = sum_k A[m,k]*B[n,k] (NT), fp32 accum via 3-term bf16 split.
// CTA 128x128, 8 warps (2M x 4N), warp tile 64x32, BK=64, 3-stage cp.async.
// EPI: 0 = fp32 store, 2 = corrected (fp32 + hi/lo + err), 3 = bias+gelu (hi/lo), 4 = bias (fp32)
template <int EPI>
__global__ void __launch_bounds__(256, 2)
gemm_mma(const bf16* __restrict__ Ahi, const bf16* __restrict__ Alo,
         const bf16* __restrict__ Bhi, const bf16* __restrict__ Blo,
         float* __restrict__ Cf, bf16* __restrict__ Chi, bf16* __restrict__ Clo,
         int K, int N,
         const float* __restrict__ bias, const float* __restrict__ td,
         const float* __restrict__ ew, float* __restrict__ errpart) {
    extern __shared__ __align__(128) char smem[];
    __shared__ float red[8];
    const uint32_t sb = smem_u32(smem);
    const int tid = threadIdx.x;
    const int wid = tid >> 5, lane = tid & 31;
    const int mBase = blockIdx.y * BM;
    const int nBase = blockIdx.x * BN;
    const int kc = K >> 6;          // 64-wide chunks per term
    const int NK = 3 * kc;

    const int wm = (wid >> 2) * 64;     // warp m offset (0/64)
    const int wn = (wid & 3) * 32;      // warp n offset

    // ldmatrix per-thread base offsets (within a stage's A/B region)
    const uint32_t a_off = (uint32_t)(wm + (lane & 15)) * ROWB + ((lane >> 4) * 8) * 2;
    const uint32_t b_off = (uint32_t)(wn + ((lane >> 4) << 3) + (lane & 7)) * ROWB
                         + (((lane >> 3) & 1) * 8) * 2;

    float acc[4][4][4];
    #pragma unroll
    for (int i = 0; i < 4; i++)
        #pragma unroll
        for (int j = 0; j < 4; j++)
            #pragma unroll
            for (int q = 0; q < 4; q++) acc[i][j][q] = 0.f;

    auto load_stage = [&](int kt, int s) {
        int term = kt / kc;
        int kk = kt - term * kc;
        const bf16* As = (term < 2) ? Ahi : Alo;
        const bf16* Bs = (term == 1) ? Blo : Bhi;
        size_t koff = (size_t)kk * BK;
        uint32_t abase = sb + s * STAGE_BYTES;
        uint32_t bbase = abase + A_BYTES;
        // A: 128 rows x 128B = 1024 chunks of 16B; 4 per thread
        #pragma unroll
        for (int r = 0; r < 4; r++) {
            int ch = tid + 256 * r;
            int row = ch >> 3, c16 = ch & 7;
            cp16(abase + row * ROWB + c16 * 16,
                 As + (size_t)(mBase + row) * K + koff + c16 * 8);
        }
        #pragma unroll
        for (int r = 0; r < 4; r++) {
            int ch = tid + 256 * r;
            int row = ch >> 3, c16 = ch & 7;
            cp16(bbase + row * ROWB + c16 * 16,
                 Bs + (size_t)(nBase + row) * K + koff + c16 * 8);
        }
        asm volatile("cp.async.commit_group;" ::: "memory");
    };

    // prologue: 2 stages in flight
    #pragma unroll
    for (int kt = 0; kt < NSTAGE - 1; kt++)
        if (kt < NK) load_stage(kt, kt);

    for (int kt = 0; kt < NK; kt++) {
        if (kt + 1 < NK) asm volatile("cp.async.wait_group 1;" ::: "memory");
        else             asm volatile("cp.async.wait_group 0;" ::: "memory");
        __syncthreads();
        {
            int nx = kt + NSTAGE - 1;
            if (nx < NK) load_stage(nx, nx % NSTAGE);
        }

        uint32_t abase = sb + (kt % NSTAGE) * STAGE_BYTES;
        uint32_t bbase = abase + A_BYTES;
        #pragma unroll
        for (int ks = 0; ks < 4; ks++) {
            uint32_t af[4][4], bfr[4][2];
            #pragma unroll
            for (int mi = 0; mi < 4; mi++)
                ldm_x4(af[mi][0], af[mi][1], af[mi][2], af[mi][3],
                       abase + a_off + mi * 16 * ROWB + ks * 32);
            #pragma unroll
            for (int n2 = 0; n2 < 2; n2++)
                ldm_x4(bfr[2*n2][0], bfr[2*n2][1], bfr[2*n2+1][0], bfr[2*n2+1][1],
                       bbase + b_off + n2 * 16 * ROWB + ks * 32);
            #pragma unroll
            for (int mi = 0; mi < 4; mi++)
                #pragma unroll
                for (int ni = 0; ni < 4; ni++)
                    mma16816(acc[mi][ni], af[mi], bfr[ni]);
        }
    }

    // ---- epilogue ----
    const int g = lane >> 2, tig = lane & 3;
    float esum = 0.f;
    float sw_ = 0.f;
    if (EPI == 2) sw_ = 1.f / (1.f + expf(-ew[0]));

    #pragma unroll
    for (int mi = 0; mi < 4; mi++) {
        #pragma unroll
        for (int half = 0; half < 2; half++) {
            int row = mBase + wm + mi * 16 + g + half * 8;
            #pragma unroll
            for (int ni = 0; ni < 4; ni++) {
                int col = nBase + wn + ni * 8 + 2 * tig;
                float c0 = acc[mi][ni][half * 2 + 0];
                float c1 = acc[mi][ni][half * 2 + 1];
                if (EPI == 2) {
                    float2 tv = *(const float2*)(td + (size_t)row * N + col);
                    float e0 = fminf(1.f, fmaxf(-1.f, c0 - tv.x));
                    float e1 = fminf(1.f, fmaxf(-1.f, c1 - tv.y));
                    esum += e0 * e0 + e1 * e1;
                    c0 -= sw_ * e0;
                    c1 -= sw_ * e1;
                } else if (EPI == 3) {
                    float2 bv = *(const float2*)(bias + col);
                    float v0 = c0 + bv.x, v1 = c1 + bv.y;
                    c0 = 0.5f * v0 * (1.f + erff(v0 * 0.70710678118f));
                    c1 = 0.5f * v1 * (1.f + erff(v1 * 0.70710678118f));
                } else if (EPI == 4) {
                    float2 bv = *(const float2*)(bias + col);
                    c0 += bv.x; c1 += bv.y;
                }
                if (EPI == 0 || EPI == 2 || EPI == 4)
                    *(float2*)(Cf + (size_t)row * N + col) = make_float2(c0, c1);
                if (EPI == 2 || EPI == 3) {
                    float r0, r1;
                    uint32_t hbits = pack_hi2(c0, c1, r0, r1);
                    uint32_t lbits = pack_lo2(r0, r1);
                    *(uint32_t*)(Chi + (size_t)row * N + col) = hbits;
                    *(uint32_t*)(Clo + (size_t)row * N + col) = lbits;
                }
            }
        }
    }

    if (EPI == 2) {
        #pragma unroll
        for (int o2 = 16; o2 > 0; o2 >>= 1)
            esum += __shfl_down_sync(0xffffffffu, esum, o2);
        if (lane == 0) red[wid] = esum;
        __syncthreads();
        if (tid == 0) {
            float s2 = 0.f;
            #pragma unroll
            for (int i = 0; i < 8; i++) s2 += red[i];
            errpart[blockIdx.y * gridDim.x + blockIdx.x] = s2;
        }
    }
}

// ====================== spectral scan ======================
__device__ __forceinline__ float2 cmulf(float2 a, float2 b) {
    return make_float2(a.x * b.x - a.y * b.y, a.x * b.y + a.y * b.x);
}
__device__ __forceinline__ void scan_consts(const float* ld, const float* fr, int f,
                                            float2& A, float2& rot) {
    float decay = 1.f / (1.f + expf(-ld[f]));
    float om = tanhf(fr[f]) * 0.1f;
    rot = make_float2(cosf(om), sinf(om));
    A = make_float2(decay * rot.x, decay * rot.y);
}

__global__ void scan_phaseA(const float* __restrict__ ld, const float* __restrict__ fr) {
    int b = blockIdx.x / CHUNKS, c = blockIdx.x % CHUNKS;
    int f = threadIdx.x;
    float2 A, rot;
    scan_consts(ld, fr, f, A, rot);
    float2 h = make_float2(0.f, 0.f);
    const float* base = g_spec + ((size_t)b * SSEQ + (size_t)c * CLEN) * TWO_F;
    #pragma unroll 4
    for (int j = 0; j < CLEN; j++) {
        float ur = base[(size_t)j * TWO_F + f];
        float ui = base[(size_t)j * TWO_F + FFREQ + f];
        float hr = A.x * h.x - A.y * h.y + ur;
        float hi = A.x * h.y + A.y * h.x + ui;
        h.x = hr; h.y = hi;
    }
    g_hend[(b * CHUNKS + c) * FFREQ + f] = h;
}

__global__ void scan_carry(const float* __restrict__ ld, const float* __restrict__ fr) {
    int b = blockIdx.x;
    int f = threadIdx.x;
    float2 A, rot;
    scan_consts(ld, fr, f, A, rot);
    float2 AL = A;
    #pragma unroll
    for (int i = 0; i < 7; i++) AL = cmulf(AL, AL);   // A^128
    float2 H = make_float2(0.f, 0.f);
    for (int c = 0; c < CHUNKS; c++) {
        g_carry[(b * CHUNKS + c) * FFREQ + f] = H;
        float2 he = g_hend[(b * CHUNKS + c) * FFREQ + f];
        float hr = AL.x * H.x - AL.y * H.y + he.x;
        float hi = AL.x * H.y + AL.y * H.x + he.y;
        H.x = hr; H.y = hi;
    }
}

__global__ void scan_phaseC(const float* __restrict__ ld, const float* __restrict__ fr) {
    int b = blockIdx.x / CHUNKS, c = blockIdx.x % CHUNKS;
    int f = threadIdx.x;
    float2 A, rot;
    scan_consts(ld, fr, f, A, rot);
    float2 h = g_carry[(b * CHUNKS + c) * FFREQ + f];
    size_t rowoff = ((size_t)b * SSEQ + (size_t)c * CLEN) * TWO_F;
    const float* base = g_spec + rowoff;
    #pragma unroll 4
    for (int j = 0; j < CLEN; j++) {
        float ur = base[(size_t)j * TWO_F + f];
        float ui = base[(size_t)j * TWO_F + FFREQ + f];
        float hr = A.x * h.x - A.y * h.y + ur;
        float hi = A.x * h.y + A.y * h.x + ui;
        h.x = hr; h.y = hi;
        float yr = rot.x * hr - rot.y * hi;
        float yi = rot.x * hi + rot.y * hr;
        size_t ir = rowoff + (size_t)j * TWO_F + f;
        size_t ii = rowoff + (size_t)j * TWO_F + FFREQ + f;
        __nv_bfloat16 hr16 = __float2bfloat16(yr);
        __nv_bfloat16 hi16 = __float2bfloat16(yi);
        g_shi[ir] = hr16;
        g_slo[ir] = __float2bfloat16(yr - __bfloat162float(hr16));
        g_shi[ii] = hi16;
        g_slo[ii] = __float2bfloat16(yi - __bfloat162float(hi16));
    }
}

// ======================= error finalize =======================
__global__ void err_finish(float* __restrict__ o) {
    int t = threadIdx.x;   // 1024 threads
    double v = (double)g_errpart[t];
    #pragma unroll
    for (int off = 16; off > 0; off >>= 1)
        v += __shfl_down_sync(0xffffffffu, v, off);
    __shared__ double sh[32];
    int w = t >> 5, l = t & 31;
    if (l == 0) sh[w] = v;
    __syncthreads();
    if (t < 32) {
        v = sh[t];
        #pragma unroll
        for (int off = 16; off > 0; off >>= 1)
            v += __shfl_down_sync(0xffffffffu, v, off);
        if (t == 0) {
            double mean = v / ((double)MROWS * (double)DDIM);
            float m = (float)mean;
            m = fminf(1.f, fmaxf(0.f, m));
            o[0] = m;
        }
    }
}

// ============================ launch ============================
extern "C" void kernel_launch(void* const* d_in, const int* in_sizes, int n_in,
                              void* d_out, int out_size) {
    const float* bu      = (const float*)d_in[0];
    const float* td      = (const float*)d_in[1];
    const float* W_spec  = (const float*)d_in[2];
    const float* log_dec = (const float*)d_in[3];
    const float* freq    = (const float*)d_in[4];
    const float* W_from  = (const float*)d_in[5];
    const float* ln1g    = (const float*)d_in[6];
    const float* ln1b    = (const float*)d_in[7];
    const float* W1      = (const float*)d_in[8];
    const float* b1      = (const float*)d_in[9];
    const float* W2      = (const float*)d_in[10];
    const float* b2      = (const float*)d_in[11];
    const float* ln2g    = (const float*)d_in[12];
    const float* ln2b    = (const float*)d_in[13];
    const float* ew      = (const float*)d_in[14];

    float* out       = (float*)d_out;
    float* corrected = out;
    float* nextpred  = out + (size_t)MROWS * DDIM;
    float* errout    = out + 2 * (size_t)MROWS * DDIM;

    bf16 *xhi, *xlo, *shi, *slo, *chi, *clo, *hhi, *hlo;
    bf16 *wsh, *wsl, *wfh, *wfl, *w1h, *w1l, *w2h, *w2l;
    float *spec, *h2, *errpart;
    cudaGetSymbolAddress((void**)&xhi, g_xhi);   cudaGetSymbolAddress((void**)&xlo, g_xlo);
    cudaGetSymbolAddress((void**)&shi, g_shi);   cudaGetSymbolAddress((void**)&slo, g_slo);
    cudaGetSymbolAddress((void**)&chi, g_chi);   cudaGetSymbolAddress((void**)&clo, g_clo);
    cudaGetSymbolAddress((void**)&hhi, g_hhi);   cudaGetSymbolAddress((void**)&hlo, g_hlo);
    cudaGetSymbolAddress((void**)&wsh, g_wspec_hi); cudaGetSymbolAddress((void**)&wsl, g_wspec_lo);
    cudaGetSymbolAddress((void**)&wfh, g_wfrom_hi); cudaGetSymbolAddress((void**)&wfl, g_wfrom_lo);
    cudaGetSymbolAddress((void**)&w1h, g_w1_hi);    cudaGetSymbolAddress((void**)&w1l, g_w1_lo);
    cudaGetSymbolAddress((void**)&w2h, g_w2_hi);    cudaGetSymbolAddress((void**)&w2l, g_w2_lo);
    cudaGetSymbolAddress((void**)&spec, g_spec);
    cudaGetSymbolAddress((void**)&h2, g_h2);
    cudaGetSymbolAddress((void**)&errpart, g_errpart);

    cudaFuncSetAttribute(gemm_mma<0>, cudaFuncAttributeMaxDynamicSharedMemorySize, SMEM_SZ);
    cudaFuncSetAttribute(gemm_mma<2>, cudaFuncAttributeMaxDynamicSharedMemorySize, SMEM_SZ);
    cudaFuncSetAttribute(gemm_mma<3>, cudaFuncAttributeMaxDynamicSharedMemorySize, SMEM_SZ);
    cudaFuncSetAttribute(gemm_mma<4>, cudaFuncAttributeMaxDynamicSharedMemorySize, SMEM_SZ);

    int n4 = TWO_F * DDIM / 4;
    int m4 = DDIM * DDIM / 4;
    split_k<<<(m4 + 255) / 256, 256>>>((const float4*)W1, (uint2*)w1h, (uint2*)w1l, m4);
    split_k<<<(m4 + 255) / 256, 256>>>((const float4*)W2, (uint2*)w2h, (uint2*)w2l, m4);
    split_k<<<(n4 + 255) / 256, 256>>>((const float4*)W_spec, (uint2*)wsh, (uint2*)wsl, n4);
    split_k<<<(n4 + 255) / 256, 256>>>((const float4*)W_from, (uint2*)wfh, (uint2*)wfl, n4);

    // LN1 -> xln hi/lo
    ln_kernel<1><<<MROWS, 256>>>(bu, ln1g, ln1b, nullptr, xhi, xlo);
    // spec = xln @ W_spec^T
    gemm_mma<0><<<dim3(TWO_F / BN, MROWS / BM), 256, SMEM_SZ>>>(
        xhi, xlo, wsh, wsl, spec, nullptr, nullptr, DDIM, TWO_F,
        nullptr, nullptr, nullptr, nullptr);
    // chunked complex scan -> sout hi/lo
    scan_phaseA<<<BBATCH * CHUNKS, FFREQ>>>(log_dec, freq);
    scan_carry<<<BBATCH, FFREQ>>>(log_dec, freq);
    scan_phaseC<<<BBATCH * CHUNKS, FFREQ>>>(log_dec, freq);
    // corrected = sout @ W_from^T (+ err)
    gemm_mma<2><<<dim3(DDIM / BN, MROWS / BM), 256, SMEM_SZ>>>(
        shi, slo, wfh, wfl, corrected, chi, clo, TWO_F, DDIM,
        nullptr, td, ew, errpart);
    err_finish<<<1, 1024>>>(errout);
    // h = gelu(corrected @ W1^T + b1)
    gemm_mma<3><<<dim3(DDIM / BN, MROWS / BM), 256, SMEM_SZ>>>(
        chi, clo, w1h, w1l, nullptr, hhi, hlo, DDIM, DDIM,
        b1, nullptr, nullptr, nullptr);
    // h2 = h @ W2^T + b2
    gemm_mma<4><<<dim3(DDIM / BN, MROWS / BM), 256, SMEM_SZ>>>(
        hhi, hlo, w2h, w2l, h2, nullptr, nullptr, DDIM, DDIM,
        b2, nullptr, nullptr, nullptr);
    // LN2 -> next_prediction
    ln_kernel<0><<<MROWS, 256>>>(h2, ln2g, ln2b, nextpred, nullptr, nullptr);
}